// round 11
// baseline (speedup 1.0000x reference)
#include <cuda_runtime.h>
#include <cuda_bf16.h>
#include <cstdint>
#include <math.h>

// Problem constants
#define Hn    81
#define G3    243          // 3*H
#define RPAD  244
#define Fn    128
#define Tn    1024
#define Bn    512
#define BPC   4
#define NCTA  128          // 512/4

// =====================================================================
// Device scratch: XG[t][ctab][b(4)][r(244)] floats = 512 MB
// =====================================================================
__device__ float4 g_xg[Tn * NCTA * RPAD];
__device__ float g_h8[Bn * 8];

// ---------- fast activations ----------
static __device__ __forceinline__ float sigm(float x) {
    x = fminf(fmaxf(x, -30.f), 30.f);
    return __fdividef(1.f, 1.f + __expf(-x));
}
static __device__ __forceinline__ float tanh_f(float x) {
    x = fminf(fmaxf(x, -20.f), 20.f);
    float e = __expf(-2.f * x);
    return __fdividef(1.f - e, 1.f + e);
}

// ---------- common mma helpers ----------
static __device__ __forceinline__ uint32_t smem_u32(const void* p) {
    uint32_t a;
    asm("{ .reg .u64 t; cvta.to.shared.u64 t, %1; cvt.u32.u64 %0, t; }"
        : "=r"(a) : "l"(p));
    return a;
}
static __device__ __forceinline__ uint32_t bfpack(float a, float b) {
    uint32_t r;
    asm("cvt.rn.bf16x2.f32 %0, %1, %2;" : "=r"(r) : "f"(b), "f"(a));
    return r;
}
static __device__ __forceinline__ void cvt8(char* thi, char* tlo, int off, float4 v) {
    uint32_t h0 = bfpack(v.x, v.y);
    uint32_t h1 = bfpack(v.z, v.w);
    float fx = __uint_as_float(h0 << 16);
    float fy = __uint_as_float(h0 & 0xffff0000u);
    float fz = __uint_as_float(h1 << 16);
    float fw = __uint_as_float(h1 & 0xffff0000u);
    uint32_t l0 = bfpack(v.x - fx, v.y - fy);
    uint32_t l1 = bfpack(v.z - fz, v.w - fw);
    *(uint2*)(thi + off) = make_uint2(h0, h1);
    *(uint2*)(tlo + off) = make_uint2(l0, l1);
}
static __device__ __forceinline__ void ldx4(uint32_t* r, uint32_t addr) {
    asm volatile("ldmatrix.sync.aligned.m8n8.x4.shared.b16 {%0,%1,%2,%3}, [%4];"
                 : "=r"(r[0]), "=r"(r[1]), "=r"(r[2]), "=r"(r[3]) : "r"(addr));
}
static __device__ __forceinline__ void ldx2(uint32_t* r, uint32_t addr) {
    asm volatile("ldmatrix.sync.aligned.m8n8.x2.shared.b16 {%0,%1}, [%2];"
                 : "=r"(r[0]), "=r"(r[1]) : "r"(addr));
}
static __device__ __forceinline__ void mma16816(float* c, const uint32_t* a,
                                                const uint32_t* b) {
    asm volatile(
        "mma.sync.aligned.m16n8k16.row.col.f32.bf16.bf16.f32 "
        "{%0,%1,%2,%3}, {%4,%5,%6,%7}, {%8,%9}, {%0,%1,%2,%3};"
        : "+f"(c[0]), "+f"(c[1]), "+f"(c[2]), "+f"(c[3])
        : "r"(a[0]), "r"(a[1]), "r"(a[2]), "r"(a[3]), "r"(b[0]), "r"(b[1]));
}

// =====================================================================
// Kernel 1: XG = x @ W_ih^T + b_ih via mma.sync bf16 (R8 winner, verbatim).
// =====================================================================
#define PITCH    272
#define TILE_SZ  (128 * PITCH)
#define SM_AHI   0
#define SM_ALO   (SM_AHI + TILE_SZ)
#define SM_BHI   (SM_ALO + TILE_SZ)
#define SM_BLO   (SM_BHI + TILE_SZ)
#define SM_BS    (4 * TILE_SZ)
#define SM_MMA_BYTES (SM_BS + 512)
#define CPITCH   132

__global__ void __launch_bounds__(256, 1) xg_mma(
    const float* __restrict__ x,
    const float* __restrict__ W_ih,
    const float* __restrict__ b_ih)
{
    extern __shared__ char sm[];
    const uint32_t smb = smem_u32(sm);
    float* bsm = (float*)(sm + SM_BS);

    const int tid  = threadIdx.x;
    const int lane = tid & 31;
    const int w    = tid >> 5;
    const int ctab = blockIdx.x;
    const int b0   = ctab * BPC;
    const int t0   = blockIdx.y * 32;
    const int mt   = blockIdx.z;
    const long sbt = (long)Tn * Fn;

    {
        const int r2 = tid >> 1;
        const int kh = tid & 1;
        {
            int rg = mt * 128 + r2;
            char* thi = sm + SM_AHI;
            char* tlo = sm + SM_ALO;
            const float4* src = (const float4*)(W_ih + (long)rg * Fn);
            bool valid = (rg < G3);
            #pragma unroll
            for (int i = 0; i < 16; i++) {
                int k = kh * 64 + i * 4;
                float4 v = valid ? src[k >> 2] : make_float4(0.f, 0.f, 0.f, 0.f);
                cvt8(thi, tlo, r2 * PITCH + k * 2, v);
            }
        }
        {
            int b = r2 & 3, tl = r2 >> 2;
            char* thi = sm + SM_BHI;
            char* tlo = sm + SM_BLO;
            const float4* src = (const float4*)(x + (long)(b0 + b) * sbt
                                                + (long)(t0 + tl) * Fn);
            #pragma unroll
            for (int i = 0; i < 16; i++) {
                int k = kh * 64 + i * 4;
                cvt8(thi, tlo, r2 * PITCH + k * 2, src[k >> 2]);
            }
        }
        if (tid < 128) {
            int rg = mt * 128 + tid;
            bsm[tid] = (rg < G3) ? b_ih[rg] : 0.f;
        }
    }
    __syncthreads();

    const int wm = (w & 3) * 32;
    const int wn = (w >> 2) * 64;

    float c[2][8][4];
    #pragma unroll
    for (int mb = 0; mb < 2; mb++)
        #pragma unroll
        for (int nb = 0; nb < 8; nb++)
            #pragma unroll
            for (int q = 0; q < 4; q++) c[mb][nb][q] = 0.f;

    int aoff[2], boff[4];
    {
        int lr = lane & 15, lk8 = (lane >> 4) * 8;
        aoff[0] = (wm + lr) * PITCH + lk8 * 2;
        aoff[1] = (wm + 16 + lr) * PITCH + lk8 * 2;
        int sel = lane >> 3;
        int nrow = wn + (lane & 7) + (sel >> 1) * 8;
        int kk = (sel & 1) * 8;
        #pragma unroll
        for (int g = 0; g < 4; g++)
            boff[g] = (nrow + 16 * g) * PITCH + kk * 2;
    }

    const uint32_t abase[3] = { smb + SM_AHI, smb + SM_ALO, smb + SM_AHI };
    const uint32_t bbase[3] = { smb + SM_BHI, smb + SM_BHI, smb + SM_BLO };

    #pragma unroll 1
    for (int pass = 0; pass < 3; pass++) {
        const uint32_t Ab = abase[pass], Bb = bbase[pass];
        #pragma unroll 1
        for (int ks = 0; ks < 8; ks++) {
            const int kb = ks * 32;
            uint32_t a[2][4], bb[8][2];
            ldx4(a[0], Ab + aoff[0] + kb);
            ldx4(a[1], Ab + aoff[1] + kb);
            #pragma unroll
            for (int g = 0; g < 4; g++) {
                uint32_t r4[4];
                ldx4(r4, Bb + boff[g] + kb);
                bb[2 * g][0] = r4[0]; bb[2 * g][1] = r4[1];
                bb[2 * g + 1][0] = r4[2]; bb[2 * g + 1][1] = r4[3];
            }
            #pragma unroll
            for (int mb = 0; mb < 2; mb++)
                #pragma unroll
                for (int nb = 0; nb < 8; nb++)
                    mma16816(c[mb][nb], a[mb], bb[nb]);
        }
    }

    __syncthreads();
    float* Cs = (float*)sm;
    {
        int lr = lane >> 2;
        int lc = (lane & 3) * 2;
        #pragma unroll
        for (int mb = 0; mb < 2; mb++) {
            int row = wm + 16 * mb + lr;
            #pragma unroll
            for (int nb = 0; nb < 8; nb++) {
                int col = wn + 8 * nb + lc;
                Cs[col * CPITCH + row]           = c[mb][nb][0];
                Cs[(col + 1) * CPITCH + row]     = c[mb][nb][1];
                Cs[col * CPITCH + row + 8]       = c[mb][nb][2];
                Cs[(col + 1) * CPITCH + row + 8] = c[mb][nb][3];
            }
        }
    }
    __syncthreads();
    {
        float* gxf = (float*)g_xg;
        int n  = tid >> 1;
        int rh = tid & 1;
        int tl = n >> 2, b = n & 3;
        long gbase = ((long)(t0 + tl) * NCTA + ctab) * 976 + b * 244 + mt * 128;
        int i0 = rh * 16;
        int i1 = rh ? ((mt == 0) ? 32 : 29) : 16;
        for (int i = i0; i < i1; i++) {
            float4 cv = *(float4*)(Cs + n * CPITCH + 4 * i);
            float4 bv = *(float4*)(bsm + 4 * i);
            cv.x += bv.x; cv.y += bv.y; cv.z += bv.z; cv.w += bv.w;
            *(float4*)(gxf + gbase + 4 * i) = cv;
        }
    }
}

// =====================================================================
// Kernel 2: TENSOR-CORE recurrence. 128 CTAs x 512 threads (16 warps).
// hg = W_hh(bf16 hi/lo, A-frags in regs for all 1024 steps) x h(bf16
// hi/lo re-split per step). M=256 pad (16 tiles), K=96 pad, N=8 (4 real).
// =====================================================================
#define KP 208   // bytes per bf16 row (96 bf16 = 192 + 16 pad; rows bank-distinct)

__global__ void __launch_bounds__(512, 1) gru_tc(
    const float* __restrict__ W_hh,  // [3H,H]
    const float* __restrict__ b_hh,  // [3H]
    const float* __restrict__ fc_w,  // [8,H]
    const float* __restrict__ fc_b)  // [8]
{
    __shared__ __align__(16) float hgS[256 * 8];       // C buffer (also A-staging scratch)
    __shared__ __align__(16) float hsS[Hn * 8];        // h state f32 [r][b]
    __shared__ __align__(16) float4 xgs[2 * RPAD];     // xg double buffer
    __shared__ __align__(16) float bsm[256];           // b_hh padded
    __shared__ __align__(16) char hbhi[8 * KP];        // h bf16 hi [b][k]
    __shared__ __align__(16) char hblo[8 * KP];        // h bf16 lo

    const int tid  = threadIdx.x;
    const int lane = tid & 31;
    const int w    = tid >> 5;        // warp = M-tile 0..15
    const int ctab = blockIdx.x;

    // ---- init: zero h (f32 + bf16 tiles incl. k/n padding), bias, xg(t=0) ----
    for (int i = tid; i < 8 * KP / 4; i += 512) {
        ((uint32_t*)hbhi)[i] = 0u;
        ((uint32_t*)hblo)[i] = 0u;
    }
    for (int i = tid; i < Hn * 8; i += 512) hsS[i] = 0.f;
    if (tid < 256) bsm[tid] = (tid < G3) ? b_hh[tid] : 0.f;
    if (tid < RPAD) xgs[tid] = g_xg[(long)ctab * RPAD + tid];

    // ---- stage W_hh A-fragments into registers (once): 16 tiles ----
    uint32_t ahi[6][4], alo[6][4];
    {
        char* scrh = (char*)hgS;          // 16 x KP = 3328 B
        char* scrl = scrh + 16 * KP;      // +3328 (fits in 8192)
        const int srow = tid >> 5;        // 0..15 row within tile
        const int kbase3 = (tid & 31) * 3;
        const int aoff = (lane & 15) * KP + ((lane >> 4) * 8) * 2;
        const uint32_t scrh_u = smem_u32(scrh), scrl_u = smem_u32(scrl);

        for (int tw = 0; tw < 16; tw++) {
            __syncthreads();
            // stage tile tw rows 16tw..16tw+15, k 0..95
            int rg = tw * 16 + srow;
            #pragma unroll
            for (int j = 0; j < 3; j++) {
                int k = kbase3 + j;
                if (k < 96) {
                    float v = (rg < G3 && k < Hn) ? W_hh[rg * Hn + k] : 0.f;
                    __nv_bfloat16 hb = __float2bfloat16(v);
                    *(__nv_bfloat16*)(scrh + srow * KP + k * 2) = hb;
                    *(__nv_bfloat16*)(scrl + srow * KP + k * 2) =
                        __float2bfloat16(v - __bfloat162float(hb));
                }
            }
            __syncthreads();
            if (w == tw) {
                #pragma unroll
                for (int kt = 0; kt < 6; kt++) {
                    ldx4(ahi[kt], scrh_u + aoff + kt * 32);
                    ldx4(alo[kt], scrl_u + aoff + kt * 32);
                }
            }
        }
    }
    __syncthreads();

    const uint32_t hbhi_u = smem_u32(hbhi);
    const uint32_t hblo_u = smem_u32(hblo);
    // B frag address (n8k16): rows = batch (lane&7), k-halves by (lane>>3)&1
    const int bofs = (lane & 7) * KP + (((lane >> 3) & 1) * 8) * 2;

    // C store mapping
    const int crow0 = w * 16 + (lane >> 2);
    const int ccol  = (lane & 3) * 2;
    const float cb0 = bsm[crow0];
    const float cb8 = bsm[crow0 + 8];

    for (int t = 0; t < Tn; t++) {
        const int cur = t & 1, nxt = cur ^ 1;

        // prefetch xg(t+1)
        float4 q = make_float4(0.f, 0.f, 0.f, 0.f);
        const bool pf = (t + 1 < Tn);
        if (pf && tid < RPAD)
            q = g_xg[((long)(t + 1) * NCTA + ctab) * RPAD + tid];

        // ---- mma: hg = Whh_hi*h_hi + Whh_lo*h_hi + Whh_hi*h_lo ----
        float cA[4] = {0.f, 0.f, 0.f, 0.f};
        float cB[4] = {0.f, 0.f, 0.f, 0.f};
        float cC[4] = {0.f, 0.f, 0.f, 0.f};
        #pragma unroll
        for (int kt = 0; kt < 6; kt++) {
            uint32_t bh[2], bl[2];
            ldx2(bh, hbhi_u + bofs + kt * 32);
            ldx2(bl, hblo_u + bofs + kt * 32);
            mma16816(cA, ahi[kt], bh);
            mma16816(cB, alo[kt], bh);
            mma16816(cC, ahi[kt], bl);
        }
        // store C (+bias) to hgS; stash prefetched xg
        {
            float2 s0 = make_float2(cA[0] + cB[0] + cC[0] + cb0,
                                    cA[1] + cB[1] + cC[1] + cb0);
            float2 s8 = make_float2(cA[2] + cB[2] + cC[2] + cb8,
                                    cA[3] + cB[3] + cC[3] + cb8);
            *(float2*)(hgS + crow0 * 8 + ccol)       = s0;
            *(float2*)(hgS + (crow0 + 8) * 8 + ccol) = s8;
        }
        if (pf && tid < RPAD) xgs[nxt * RPAD + tid] = q;
        __syncthreads();

        // ---- gate combine: 81 hidden x 4 batches ----
        if (tid < Hn * 4) {
            int r = tid >> 2, b = tid & 3;
            const float* xgc = (const float*)(xgs + cur * RPAD) + b * 244;
            float hr = hgS[r * 8 + b];
            float hz = hgS[(Hn + r) * 8 + b];
            float hn = hgS[(2 * Hn + r) * 8 + b];
            float xr = xgc[r];
            float xz = xgc[Hn + r];
            float xn = xgc[2 * Hn + r];
            float rr = sigm(xr + hr);
            float z  = sigm(xz + hz);
            float n  = tanh_f(xn + rr * hn);
            float hnew = (1.f - z) * n + z * hsS[r * 8 + b];
            hsS[r * 8 + b] = hnew;
            __nv_bfloat16 hb = __float2bfloat16(hnew);
            *(__nv_bfloat16*)(hbhi + b * KP + r * 2) = hb;
            *(__nv_bfloat16*)(hblo + b * KP + r * 2) =
                __float2bfloat16(hnew - __bfloat162float(hb));
        }
        __syncthreads();
    }

    // ---- head stage 1: out8 = silu(h_last @ fc_w^T + fc_b) ----
    if (tid < 32) {
        int b = tid >> 3, f = tid & 7;
        float a = fc_b[f];
        #pragma unroll 27
        for (int j = 0; j < Hn; j++) a += hsS[j * 8 + b] * fc_w[f * Hn + j];
        a = a * sigm(a);
        g_h8[(ctab * BPC + b) * 8 + f] = a;
    }
}

// =====================================================================
// Kernel 3: BN(8) -> fc1 -> silu -> BN(4) -> fc2. One CTA, 512 threads.
// =====================================================================
__global__ void __launch_bounds__(Bn) head_kernel(
    const float* __restrict__ g1, const float* __restrict__ beta1,
    const float* __restrict__ fc1_w, const float* __restrict__ fc1_b,
    const float* __restrict__ g2, const float* __restrict__ beta2,
    const float* __restrict__ fc2_w, const float* __restrict__ fc2_b,
    float* __restrict__ out)
{
    __shared__ float s8[Bn * 8];
    __shared__ float s4[Bn * 4];
    __shared__ float mu1[8], iv1[8], mu2[4], iv2[4];
    const int tid = threadIdx.x;

    for (int i = tid; i < Bn * 8; i += Bn) s8[i] = g_h8[i];
    __syncthreads();

    if (tid < 8) {
        float s = 0.f, ss = 0.f;
        for (int b = 0; b < Bn; b++) { float v = s8[b * 8 + tid]; s += v; ss += v * v; }
        float m = s * (1.f / Bn);
        float var = ss * (1.f / Bn) - m * m;
        mu1[tid] = m;
        iv1[tid] = rsqrtf(var + 1e-5f);
    }
    __syncthreads();

    {
        int b = tid;
        float y[8];
        #pragma unroll
        for (int f = 0; f < 8; f++)
            y[f] = (s8[b * 8 + f] - mu1[f]) * iv1[f] * g1[f] + beta1[f];
        #pragma unroll
        for (int o = 0; o < 4; o++) {
            float a = fc1_b[o];
            #pragma unroll
            for (int f = 0; f < 8; f++) a += y[f] * fc1_w[o * 8 + f];
            a = a * sigm(a);
            s4[b * 4 + o] = a;
        }
    }
    __syncthreads();

    if (tid < 4) {
        float s = 0.f, ss = 0.f;
        for (int b = 0; b < Bn; b++) { float v = s4[b * 4 + tid]; s += v; ss += v * v; }
        float m = s * (1.f / Bn);
        float var = ss * (1.f / Bn) - m * m;
        mu2[tid] = m;
        iv2[tid] = rsqrtf(var + 1e-5f);
    }
    __syncthreads();

    {
        int b = tid;
        float a = fc2_b[0];
        #pragma unroll
        for (int o = 0; o < 4; o++)
            a += ((s4[b * 4 + o] - mu2[o]) * iv2[o] * g2[o] + beta2[o]) * fc2_w[o];
        out[b] = a;
    }
}

// =====================================================================
extern "C" void kernel_launch(void* const* d_in, const int* in_sizes, int n_in,
                              void* d_out, int out_size) {
    const float* x     = (const float*)d_in[0];
    const float* W_ih  = (const float*)d_in[1];
    const float* W_hh  = (const float*)d_in[2];
    const float* b_ih  = (const float*)d_in[3];
    const float* b_hh  = (const float*)d_in[4];
    const float* fc_w  = (const float*)d_in[5];
    const float* fc_b  = (const float*)d_in[6];
    const float* g1    = (const float*)d_in[7];
    const float* beta1 = (const float*)d_in[8];
    const float* fc1_w = (const float*)d_in[9];
    const float* fc1_b = (const float*)d_in[10];
    const float* g2    = (const float*)d_in[11];
    const float* beta2 = (const float*)d_in[12];
    const float* fc2_w = (const float*)d_in[13];
    const float* fc2_b = (const float*)d_in[14];
    float* out = (float*)d_out;

    cudaFuncSetAttribute(xg_mma, cudaFuncAttributeMaxDynamicSharedMemorySize, SM_MMA_BYTES);

    xg_mma<<<dim3(NCTA, 32, 2), 256, SM_MMA_BYTES>>>(x, W_ih, b_ih);
    gru_tc<<<NCTA, 512>>>(W_hh, b_hh, fc_w, fc_b);
    head_kernel<<<1, Bn>>>(g1, beta1, fc1_w, fc1_b, g2, beta2, fc2_w, fc2_b, out);
}

// round 12
// speedup vs baseline: 1.1952x; 1.1952x over previous
#include <cuda_runtime.h>
#include <cuda_bf16.h>
#include <cstdint>
#include <math.h>

// Problem constants
#define Hn    81
#define G3    243          // 3*H
#define RPAD  244
#define Fn    128
#define Tn    1024
#define Bn    512
#define BPC   4
#define NCTA  128          // 512/4

// =====================================================================
// Device scratch: XG[t][ctab][b(4)][r(244)] floats = 512 MB
// =====================================================================
__device__ float4 g_xg[Tn * NCTA * RPAD];
__device__ float g_h8[Bn * 8];

// ---------- fast activations ----------
static __device__ __forceinline__ float sigm(float x) {
    x = fminf(fmaxf(x, -30.f), 30.f);
    return __fdividef(1.f, 1.f + __expf(-x));
}
static __device__ __forceinline__ float tanh_f(float x) {
    x = fminf(fmaxf(x, -20.f), 20.f);
    float e = __expf(-2.f * x);
    return __fdividef(1.f - e, 1.f + e);
}

// ---------- common mma helpers ----------
static __device__ __forceinline__ uint32_t smem_u32(const void* p) {
    uint32_t a;
    asm("{ .reg .u64 t; cvta.to.shared.u64 t, %1; cvt.u32.u64 %0, t; }"
        : "=r"(a) : "l"(p));
    return a;
}
static __device__ __forceinline__ uint32_t bfpack(float a, float b) {
    uint32_t r;
    asm("cvt.rn.bf16x2.f32 %0, %1, %2;" : "=r"(r) : "f"(b), "f"(a));
    return r;
}
static __device__ __forceinline__ void cvt8(char* thi, char* tlo, int off, float4 v) {
    uint32_t h0 = bfpack(v.x, v.y);
    uint32_t h1 = bfpack(v.z, v.w);
    float fx = __uint_as_float(h0 << 16);
    float fy = __uint_as_float(h0 & 0xffff0000u);
    float fz = __uint_as_float(h1 << 16);
    float fw = __uint_as_float(h1 & 0xffff0000u);
    uint32_t l0 = bfpack(v.x - fx, v.y - fy);
    uint32_t l1 = bfpack(v.z - fz, v.w - fw);
    *(uint2*)(thi + off) = make_uint2(h0, h1);
    *(uint2*)(tlo + off) = make_uint2(l0, l1);
}
static __device__ __forceinline__ void ldx4(uint32_t* r, uint32_t addr) {
    asm volatile("ldmatrix.sync.aligned.m8n8.x4.shared.b16 {%0,%1,%2,%3}, [%4];"
                 : "=r"(r[0]), "=r"(r[1]), "=r"(r[2]), "=r"(r[3]) : "r"(addr));
}
static __device__ __forceinline__ void ldx2(uint32_t* r, uint32_t addr) {
    asm volatile("ldmatrix.sync.aligned.m8n8.x2.shared.b16 {%0,%1}, [%2];"
                 : "=r"(r[0]), "=r"(r[1]) : "r"(addr));
}
static __device__ __forceinline__ void mma16816(float* c, const uint32_t* a,
                                                const uint32_t* b) {
    asm volatile(
        "mma.sync.aligned.m16n8k16.row.col.f32.bf16.bf16.f32 "
        "{%0,%1,%2,%3}, {%4,%5,%6,%7}, {%8,%9}, {%0,%1,%2,%3};"
        : "+f"(c[0]), "+f"(c[1]), "+f"(c[2]), "+f"(c[3])
        : "r"(a[0]), "r"(a[1]), "r"(a[2]), "r"(a[3]), "r"(b[0]), "r"(b[1]));
}

// =====================================================================
// Kernel 1: XG = x @ W_ih^T + b_ih via mma.sync bf16 (R8 winner, verbatim).
// =====================================================================
#define PITCH    272
#define TILE_SZ  (128 * PITCH)
#define SM_AHI   0
#define SM_ALO   (SM_AHI + TILE_SZ)
#define SM_BHI   (SM_ALO + TILE_SZ)
#define SM_BLO   (SM_BHI + TILE_SZ)
#define SM_BS    (4 * TILE_SZ)
#define SM_MMA_BYTES (SM_BS + 512)
#define CPITCH   132

__global__ void __launch_bounds__(256, 1) xg_mma(
    const float* __restrict__ x,
    const float* __restrict__ W_ih,
    const float* __restrict__ b_ih)
{
    extern __shared__ char sm[];
    const uint32_t smb = smem_u32(sm);
    float* bsm = (float*)(sm + SM_BS);

    const int tid  = threadIdx.x;
    const int lane = tid & 31;
    const int w    = tid >> 5;
    const int ctab = blockIdx.x;
    const int b0   = ctab * BPC;
    const int t0   = blockIdx.y * 32;
    const int mt   = blockIdx.z;
    const long sbt = (long)Tn * Fn;

    {
        const int r2 = tid >> 1;
        const int kh = tid & 1;
        {
            int rg = mt * 128 + r2;
            char* thi = sm + SM_AHI;
            char* tlo = sm + SM_ALO;
            const float4* src = (const float4*)(W_ih + (long)rg * Fn);
            bool valid = (rg < G3);
            #pragma unroll
            for (int i = 0; i < 16; i++) {
                int k = kh * 64 + i * 4;
                float4 v = valid ? src[k >> 2] : make_float4(0.f, 0.f, 0.f, 0.f);
                cvt8(thi, tlo, r2 * PITCH + k * 2, v);
            }
        }
        {
            int b = r2 & 3, tl = r2 >> 2;
            char* thi = sm + SM_BHI;
            char* tlo = sm + SM_BLO;
            const float4* src = (const float4*)(x + (long)(b0 + b) * sbt
                                                + (long)(t0 + tl) * Fn);
            #pragma unroll
            for (int i = 0; i < 16; i++) {
                int k = kh * 64 + i * 4;
                cvt8(thi, tlo, r2 * PITCH + k * 2, src[k >> 2]);
            }
        }
        if (tid < 128) {
            int rg = mt * 128 + tid;
            bsm[tid] = (rg < G3) ? b_ih[rg] : 0.f;
        }
    }
    __syncthreads();

    const int wm = (w & 3) * 32;
    const int wn = (w >> 2) * 64;

    float c[2][8][4];
    #pragma unroll
    for (int mb = 0; mb < 2; mb++)
        #pragma unroll
        for (int nb = 0; nb < 8; nb++)
            #pragma unroll
            for (int q = 0; q < 4; q++) c[mb][nb][q] = 0.f;

    int aoff[2], boff[4];
    {
        int lr = lane & 15, lk8 = (lane >> 4) * 8;
        aoff[0] = (wm + lr) * PITCH + lk8 * 2;
        aoff[1] = (wm + 16 + lr) * PITCH + lk8 * 2;
        int sel = lane >> 3;
        int nrow = wn + (lane & 7) + (sel >> 1) * 8;
        int kk = (sel & 1) * 8;
        #pragma unroll
        for (int g = 0; g < 4; g++)
            boff[g] = (nrow + 16 * g) * PITCH + kk * 2;
    }

    const uint32_t abase[3] = { smb + SM_AHI, smb + SM_ALO, smb + SM_AHI };
    const uint32_t bbase[3] = { smb + SM_BHI, smb + SM_BHI, smb + SM_BLO };

    #pragma unroll 1
    for (int pass = 0; pass < 3; pass++) {
        const uint32_t Ab = abase[pass], Bb = bbase[pass];
        #pragma unroll 1
        for (int ks = 0; ks < 8; ks++) {
            const int kb = ks * 32;
            uint32_t a[2][4], bb[8][2];
            ldx4(a[0], Ab + aoff[0] + kb);
            ldx4(a[1], Ab + aoff[1] + kb);
            #pragma unroll
            for (int g = 0; g < 4; g++) {
                uint32_t r4[4];
                ldx4(r4, Bb + boff[g] + kb);
                bb[2 * g][0] = r4[0]; bb[2 * g][1] = r4[1];
                bb[2 * g + 1][0] = r4[2]; bb[2 * g + 1][1] = r4[3];
            }
            #pragma unroll
            for (int mb = 0; mb < 2; mb++)
                #pragma unroll
                for (int nb = 0; nb < 8; nb++)
                    mma16816(c[mb][nb], a[mb], bb[nb]);
        }
    }

    __syncthreads();
    float* Cs = (float*)sm;
    {
        int lr = lane >> 2;
        int lc = (lane & 3) * 2;
        #pragma unroll
        for (int mb = 0; mb < 2; mb++) {
            int row = wm + 16 * mb + lr;
            #pragma unroll
            for (int nb = 0; nb < 8; nb++) {
                int col = wn + 8 * nb + lc;
                Cs[col * CPITCH + row]           = c[mb][nb][0];
                Cs[(col + 1) * CPITCH + row]     = c[mb][nb][1];
                Cs[col * CPITCH + row + 8]       = c[mb][nb][2];
                Cs[(col + 1) * CPITCH + row + 8] = c[mb][nb][3];
            }
        }
    }
    __syncthreads();
    {
        float* gxf = (float*)g_xg;
        int n  = tid >> 1;
        int rh = tid & 1;
        int tl = n >> 2, b = n & 3;
        long gbase = ((long)(t0 + tl) * NCTA + ctab) * 976 + b * 244 + mt * 128;
        int i0 = rh * 16;
        int i1 = rh ? ((mt == 0) ? 32 : 29) : 16;
        for (int i = i0; i < i1; i++) {
            float4 cv = *(float4*)(Cs + n * CPITCH + 4 * i);
            float4 bv = *(float4*)(bsm + 4 * i);
            cv.x += bv.x; cv.y += bv.y; cv.z += bv.z; cv.w += bv.w;
            *(float4*)(gxf + gbase + 4 * i) = cv;
        }
    }
}

// =====================================================================
// Kernel 2: TENSOR-CORE recurrence with DISTANCE-2 xg prefetch.
// 128 CTAs x 512 threads (16 warps = 16 M-tiles).
// =====================================================================
#define KP 208   // bytes per bf16 row (96 bf16 = 192 + 16 pad)

__global__ void __launch_bounds__(512, 1) gru_tc(
    const float* __restrict__ W_hh,  // [3H,H]
    const float* __restrict__ b_hh,  // [3H]
    const float* __restrict__ fc_w,  // [8,H]
    const float* __restrict__ fc_b)  // [8]
{
    __shared__ __align__(16) float hgS[256 * 8];       // C buffer / A-staging scratch
    __shared__ __align__(16) float hsS[Hn * 8];        // h state f32 [r][b]
    __shared__ __align__(16) float4 xgs[2 * RPAD];     // xg double buffer
    __shared__ __align__(16) float bsm[256];           // b_hh padded
    __shared__ __align__(16) char hbhi[8 * KP];        // h bf16 hi [b][k]
    __shared__ __align__(16) char hblo[8 * KP];        // h bf16 lo

    const int tid  = threadIdx.x;
    const int lane = tid & 31;
    const int w    = tid >> 5;        // warp = M-tile 0..15
    const int ctab = blockIdx.x;

    // ---- init ----
    for (int i = tid; i < 8 * KP / 4; i += 512) {
        ((uint32_t*)hbhi)[i] = 0u;
        ((uint32_t*)hblo)[i] = 0u;
    }
    for (int i = tid; i < Hn * 8; i += 512) hsS[i] = 0.f;
    if (tid < 256) bsm[tid] = (tid < G3) ? b_hh[tid] : 0.f;
    if (tid < RPAD) xgs[tid] = g_xg[(long)ctab * RPAD + tid];   // t=0 -> buf 0

    // ---- stage W_hh A-fragments into registers (once): 16 tiles ----
    uint32_t ahi[6][4], alo[6][4];
    {
        char* scrh = (char*)hgS;          // 16 x KP = 3328 B
        char* scrl = scrh + 16 * KP;      // fits in hgS (8192 B)
        const int srow = tid >> 5;
        const int kbase3 = (tid & 31) * 3;
        const int aoff = (lane & 15) * KP + ((lane >> 4) * 8) * 2;
        const uint32_t scrh_u = smem_u32(scrh), scrl_u = smem_u32(scrl);

        for (int tw = 0; tw < 16; tw++) {
            __syncthreads();
            int rg = tw * 16 + srow;
            #pragma unroll
            for (int j = 0; j < 3; j++) {
                int k = kbase3 + j;
                if (k < 96) {
                    float v = (rg < G3 && k < Hn) ? W_hh[rg * Hn + k] : 0.f;
                    __nv_bfloat16 hb = __float2bfloat16(v);
                    *(__nv_bfloat16*)(scrh + srow * KP + k * 2) = hb;
                    *(__nv_bfloat16*)(scrl + srow * KP + k * 2) =
                        __float2bfloat16(v - __bfloat162float(hb));
                }
            }
            __syncthreads();
            if (w == tw) {
                #pragma unroll
                for (int kt = 0; kt < 6; kt++) {
                    ldx4(ahi[kt], scrh_u + aoff + kt * 32);
                    ldx4(alo[kt], scrl_u + aoff + kt * 32);
                }
            }
        }
    }

    // preload q1 = xg(t=1) (a full step ahead of its smem stash)
    float4 q1 = make_float4(0.f, 0.f, 0.f, 0.f);
    if (tid < RPAD) q1 = g_xg[((long)1 * NCTA + ctab) * RPAD + tid];
    __syncthreads();

    const uint32_t hbhi_u = smem_u32(hbhi);
    const uint32_t hblo_u = smem_u32(hblo);
    const int bofs = (lane & 7) * KP + (((lane >> 3) & 1) * 8) * 2;

    const int crow0 = w * 16 + (lane >> 2);
    const int ccol  = (lane & 3) * 2;
    const float cb0 = bsm[crow0];
    const float cb8 = bsm[crow0 + 8];

    for (int t = 0; t < Tn; t++) {
        const int cur = t & 1, nxt = cur ^ 1;

        // issue prefetch of xg(t+2) -- consumed NEXT step (distance 2)
        float4 q2 = make_float4(0.f, 0.f, 0.f, 0.f);
        if (t + 2 < Tn && tid < RPAD)
            q2 = g_xg[((long)(t + 2) * NCTA + ctab) * RPAD + tid];

        // ---- mma: hg = Whh_hi*h_hi + Whh_lo*h_hi + Whh_hi*h_lo ----
        float cA[4] = {0.f, 0.f, 0.f, 0.f};
        float cB[4] = {0.f, 0.f, 0.f, 0.f};
        float cC[4] = {0.f, 0.f, 0.f, 0.f};
        #pragma unroll
        for (int kt = 0; kt < 6; kt++) {
            uint32_t bh[2], bl[2];
            ldx2(bh, hbhi_u + bofs + kt * 32);
            ldx2(bl, hblo_u + bofs + kt * 32);
            mma16816(cA, ahi[kt], bh);
            mma16816(cB, alo[kt], bh);
            mma16816(cC, ahi[kt], bl);
        }
        {
            float2 s0 = make_float2(cA[0] + cB[0] + cC[0] + cb0,
                                    cA[1] + cB[1] + cC[1] + cb0);
            float2 s8 = make_float2(cA[2] + cB[2] + cC[2] + cb8,
                                    cA[3] + cB[3] + cC[3] + cb8);
            *(float2*)(hgS + crow0 * 8 + ccol)       = s0;
            *(float2*)(hgS + (crow0 + 8) * 8 + ccol) = s8;
        }
        // stash xg(t+1): q1 was loaded a FULL step ago -> latency hidden
        if (t + 1 < Tn && tid < RPAD) xgs[nxt * RPAD + tid] = q1;
        __syncthreads();

        // ---- gate combine: 81 hidden x 4 batches ----
        if (tid < Hn * 4) {
            int r = tid >> 2, b = tid & 3;
            const float* xgc = (const float*)(xgs + cur * RPAD) + b * 244;
            float hr = hgS[r * 8 + b];
            float hz = hgS[(Hn + r) * 8 + b];
            float hn = hgS[(2 * Hn + r) * 8 + b];
            float xr = xgc[r];
            float xz = xgc[Hn + r];
            float xn = xgc[2 * Hn + r];
            float rr = sigm(xr + hr);
            float z  = sigm(xz + hz);
            float n  = tanh_f(xn + rr * hn);
            float hnew = (1.f - z) * n + z * hsS[r * 8 + b];
            hsS[r * 8 + b] = hnew;
            __nv_bfloat16 hb = __float2bfloat16(hnew);
            *(__nv_bfloat16*)(hbhi + b * KP + r * 2) = hb;
            *(__nv_bfloat16*)(hblo + b * KP + r * 2) =
                __float2bfloat16(hnew - __bfloat162float(hb));
        }
        q1 = q2;
        __syncthreads();
    }

    // ---- head stage 1: out8 = silu(h_last @ fc_w^T + fc_b) ----
    if (tid < 32) {
        int b = tid >> 3, f = tid & 7;
        float a = fc_b[f];
        #pragma unroll 27
        for (int j = 0; j < Hn; j++) a += hsS[j * 8 + b] * fc_w[f * Hn + j];
        a = a * sigm(a);
        g_h8[(ctab * BPC + b) * 8 + f] = a;
    }
}

// =====================================================================
// Kernel 3: BN(8) -> fc1 -> silu -> BN(4) -> fc2. One CTA, 512 threads.
// =====================================================================
__global__ void __launch_bounds__(Bn) head_kernel(
    const float* __restrict__ g1, const float* __restrict__ beta1,
    const float* __restrict__ fc1_w, const float* __restrict__ fc1_b,
    const float* __restrict__ g2, const float* __restrict__ beta2,
    const float* __restrict__ fc2_w, const float* __restrict__ fc2_b,
    float* __restrict__ out)
{
    __shared__ float s8[Bn * 8];
    __shared__ float s4[Bn * 4];
    __shared__ float mu1[8], iv1[8], mu2[4], iv2[4];
    const int tid = threadIdx.x;

    for (int i = tid; i < Bn * 8; i += Bn) s8[i] = g_h8[i];
    __syncthreads();

    if (tid < 8) {
        float s = 0.f, ss = 0.f;
        for (int b = 0; b < Bn; b++) { float v = s8[b * 8 + tid]; s += v; ss += v * v; }
        float m = s * (1.f / Bn);
        float var = ss * (1.f / Bn) - m * m;
        mu1[tid] = m;
        iv1[tid] = rsqrtf(var + 1e-5f);
    }
    __syncthreads();

    {
        int b = tid;
        float y[8];
        #pragma unroll
        for (int f = 0; f < 8; f++)
            y[f] = (s8[b * 8 + f] - mu1[f]) * iv1[f] * g1[f] + beta1[f];
        #pragma unroll
        for (int o = 0; o < 4; o++) {
            float a = fc1_b[o];
            #pragma unroll
            for (int f = 0; f < 8; f++) a += y[f] * fc1_w[o * 8 + f];
            a = a * sigm(a);
            s4[b * 4 + o] = a;
        }
    }
    __syncthreads();

    if (tid < 4) {
        float s = 0.f, ss = 0.f;
        for (int b = 0; b < Bn; b++) { float v = s4[b * 4 + tid]; s += v; ss += v * v; }
        float m = s * (1.f / Bn);
        float var = ss * (1.f / Bn) - m * m;
        mu2[tid] = m;
        iv2[tid] = rsqrtf(var + 1e-5f);
    }
    __syncthreads();

    {
        int b = tid;
        float a = fc2_b[0];
        #pragma unroll
        for (int o = 0; o < 4; o++)
            a += ((s4[b * 4 + o] - mu2[o]) * iv2[o] * g2[o] + beta2[o]) * fc2_w[o];
        out[b] = a;
    }
}

// =====================================================================
extern "C" void kernel_launch(void* const* d_in, const int* in_sizes, int n_in,
                              void* d_out, int out_size) {
    const float* x     = (const float*)d_in[0];
    const float* W_ih  = (const float*)d_in[1];
    const float* W_hh  = (const float*)d_in[2];
    const float* b_ih  = (const float*)d_in[3];
    const float* b_hh  = (const float*)d_in[4];
    const float* fc_w  = (const float*)d_in[5];
    const float* fc_b  = (const float*)d_in[6];
    const float* g1    = (const float*)d_in[7];
    const float* beta1 = (const float*)d_in[8];
    const float* fc1_w = (const float*)d_in[9];
    const float* fc1_b = (const float*)d_in[10];
    const float* g2    = (const float*)d_in[11];
    const float* beta2 = (const float*)d_in[12];
    const float* fc2_w = (const float*)d_in[13];
    const float* fc2_b = (const float*)d_in[14];
    float* out = (float*)d_out;

    cudaFuncSetAttribute(xg_mma, cudaFuncAttributeMaxDynamicSharedMemorySize, SM_MMA_BYTES);

    xg_mma<<<dim3(NCTA, 32, 2), 256, SM_MMA_BYTES>>>(x, W_ih, b_ih);
    gru_tc<<<NCTA, 512>>>(W_hh, b_hh, fc_w, fc_b);
    head_kernel<<<1, Bn>>>(g1, beta1, fc1_w, fc1_b, g2, beta2, fc2_w, fc2_b, out);
}

// round 13
// speedup vs baseline: 1.2806x; 1.0715x over previous
#include <cuda_runtime.h>
#include <cuda_bf16.h>
#include <cstdint>
#include <math.h>

// Problem constants
#define Hn    81
#define G3    243          // 3*H
#define RPAD  244
#define Fn    128
#define Tn    1024
#define Bn    512
#define BPC   4
#define NCTA  128          // 512/4

// =====================================================================
// Device scratch: XG[t][ctab][b(4)][r(244)] floats = 512 MB
// =====================================================================
__device__ float4 g_xg[Tn * NCTA * RPAD];
__device__ float g_h8[Bn * 8];

// ---------- fast activations ----------
static __device__ __forceinline__ float sigm(float x) {
    x = fminf(fmaxf(x, -30.f), 30.f);
    return __fdividef(1.f, 1.f + __expf(-x));
}
static __device__ __forceinline__ float tanh_f(float x) {
    x = fminf(fmaxf(x, -20.f), 20.f);
    float e = __expf(-2.f * x);
    return __fdividef(1.f - e, 1.f + e);
}

// ---------- common mma helpers ----------
static __device__ __forceinline__ uint32_t smem_u32(const void* p) {
    uint32_t a;
    asm("{ .reg .u64 t; cvta.to.shared.u64 t, %1; cvt.u32.u64 %0, t; }"
        : "=r"(a) : "l"(p));
    return a;
}
static __device__ __forceinline__ uint32_t bfpack(float a, float b) {
    uint32_t r;
    asm("cvt.rn.bf16x2.f32 %0, %1, %2;" : "=r"(r) : "f"(b), "f"(a));
    return r;
}
static __device__ __forceinline__ void cvt8(char* thi, char* tlo, int off, float4 v) {
    uint32_t h0 = bfpack(v.x, v.y);
    uint32_t h1 = bfpack(v.z, v.w);
    float fx = __uint_as_float(h0 << 16);
    float fy = __uint_as_float(h0 & 0xffff0000u);
    float fz = __uint_as_float(h1 << 16);
    float fw = __uint_as_float(h1 & 0xffff0000u);
    uint32_t l0 = bfpack(v.x - fx, v.y - fy);
    uint32_t l1 = bfpack(v.z - fz, v.w - fw);
    *(uint2*)(thi + off) = make_uint2(h0, h1);
    *(uint2*)(tlo + off) = make_uint2(l0, l1);
}
static __device__ __forceinline__ void ldx4(uint32_t* r, uint32_t addr) {
    asm volatile("ldmatrix.sync.aligned.m8n8.x4.shared.b16 {%0,%1,%2,%3}, [%4];"
                 : "=r"(r[0]), "=r"(r[1]), "=r"(r[2]), "=r"(r[3]) : "r"(addr));
}
static __device__ __forceinline__ void ldx2(uint32_t* r, uint32_t addr) {
    asm volatile("ldmatrix.sync.aligned.m8n8.x2.shared.b16 {%0,%1}, [%2];"
                 : "=r"(r[0]), "=r"(r[1]) : "r"(addr));
}
static __device__ __forceinline__ void mma16816(float* c, const uint32_t* a,
                                                const uint32_t* b) {
    asm volatile(
        "mma.sync.aligned.m16n8k16.row.col.f32.bf16.bf16.f32 "
        "{%0,%1,%2,%3}, {%4,%5,%6,%7}, {%8,%9}, {%0,%1,%2,%3};"
        : "+f"(c[0]), "+f"(c[1]), "+f"(c[2]), "+f"(c[3])
        : "r"(a[0]), "r"(a[1]), "r"(a[2]), "r"(a[3]), "r"(b[0]), "r"(b[1]));
}

// =====================================================================
// Kernel 1 (v5): XG = x @ W_ih^T + b_ih. K-chunked tiles (74 KB smem)
// -> 2 CTAs/SM; interleaved hi/lo passes (12 ldmatrix / 48 mma per
// k-step). grid (128 ctab, 32 tchunk, 2 mtile) x 256 threads.
// =====================================================================
#define KPITCH   144                     // 64 bf16 + 16B pad
#define TILE_SZ  (128 * KPITCH)          // 18432
#define SM_AHI   0
#define SM_ALO   (SM_AHI + TILE_SZ)
#define SM_BHI   (SM_ALO + TILE_SZ)
#define SM_BLO   (SM_BHI + TILE_SZ)
#define SM_BS    (4 * TILE_SZ)           // 73728
#define SM_MMA_BYTES (SM_BS + 512)       // 74240
#define CPITCH   132

__global__ void __launch_bounds__(256, 2) xg_mma(
    const float* __restrict__ x,
    const float* __restrict__ W_ih,
    const float* __restrict__ b_ih)
{
    extern __shared__ char sm[];
    const uint32_t smb = smem_u32(sm);
    float* bsm = (float*)(sm + SM_BS);

    const int tid  = threadIdx.x;
    const int lane = tid & 31;
    const int w    = tid >> 5;
    const int ctab = blockIdx.x;
    const int b0   = ctab * BPC;
    const int t0   = blockIdx.y * 32;
    const int mt   = blockIdx.z;
    const long sbt = (long)Tn * Fn;

    const int wm = (w & 3) * 32;
    const int wn = (w >> 2) * 64;

    int aoff[2], boff[2][2];
    {
        int lr = lane & 15, lk8 = (lane >> 4) * 8;
        aoff[0] = (wm + lr) * KPITCH + lk8 * 2;
        aoff[1] = (wm + 16 + lr) * KPITCH + lk8 * 2;
        int sel = lane >> 3;
        int kk = (sel & 1) * 8;
        #pragma unroll
        for (int nh = 0; nh < 2; nh++) {
            int nrow = wn + nh * 32 + (lane & 7) + (sel >> 1) * 8;
            boff[nh][0] = nrow * KPITCH + kk * 2;
            boff[nh][1] = (nrow + 16) * KPITCH + kk * 2;
        }
    }
    const int r2 = tid >> 1, kh = tid & 1;
    const int bcol = r2 & 3, tcol = r2 >> 2;

    float c[2][8][4];
    #pragma unroll
    for (int mb = 0; mb < 2; mb++)
        #pragma unroll
        for (int nb = 0; nb < 8; nb++)
            #pragma unroll
            for (int q = 0; q < 4; q++) c[mb][nb][q] = 0.f;

    #pragma unroll 1
    for (int kc = 0; kc < 2; kc++) {
        // ---- stage A (W rows) and B (x cols), this 64-wide K-chunk ----
        {
            int rg = mt * 128 + r2;
            bool va = (rg < G3);
            const float4* srcA = (const float4*)(W_ih + (long)rg * Fn
                                                 + kc * 64 + kh * 32);
            const float4* srcB = (const float4*)(x + (long)(b0 + bcol) * sbt
                                                 + (long)(t0 + tcol) * Fn
                                                 + kc * 64 + kh * 32);
            #pragma unroll
            for (int i = 0; i < 8; i++) {
                int off = r2 * KPITCH + (kh * 32 + 4 * i) * 2;
                float4 va4 = va ? srcA[i] : make_float4(0.f, 0.f, 0.f, 0.f);
                cvt8(sm + SM_AHI, sm + SM_ALO, off, va4);
                cvt8(sm + SM_BHI, sm + SM_BLO, off, srcB[i]);
            }
        }
        __syncthreads();

        // ---- mma, interleaved hi/lo passes: 4 ksteps of 16 ----
        #pragma unroll 1
        for (int ks = 0; ks < 4; ks++) {
            const int kb = ks * 32;
            uint32_t ahi[2][4], alo[2][4];
            ldx4(ahi[0], smb + SM_AHI + aoff[0] + kb);
            ldx4(ahi[1], smb + SM_AHI + aoff[1] + kb);
            ldx4(alo[0], smb + SM_ALO + aoff[0] + kb);
            ldx4(alo[1], smb + SM_ALO + aoff[1] + kb);
            #pragma unroll
            for (int nh = 0; nh < 2; nh++) {
                uint32_t bh[4][2], bl[4][2];
                #pragma unroll
                for (int g = 0; g < 2; g++) {
                    uint32_t r4[4];
                    ldx4(r4, smb + SM_BHI + boff[nh][g] + kb);
                    bh[2*g][0] = r4[0]; bh[2*g][1] = r4[1];
                    bh[2*g+1][0] = r4[2]; bh[2*g+1][1] = r4[3];
                    ldx4(r4, smb + SM_BLO + boff[nh][g] + kb);
                    bl[2*g][0] = r4[0]; bl[2*g][1] = r4[1];
                    bl[2*g+1][0] = r4[2]; bl[2*g+1][1] = r4[3];
                }
                #pragma unroll
                for (int mb = 0; mb < 2; mb++)
                    #pragma unroll
                    for (int j = 0; j < 4; j++) {
                        float* cc = c[mb][nh * 4 + j];
                        mma16816(cc, ahi[mb], bh[j]);
                        mma16816(cc, alo[mb], bh[j]);
                        mma16816(cc, ahi[mb], bl[j]);
                    }
            }
        }
        __syncthreads();   // tiles free for restage / Cs overwrite
    }

    // ---- epilogue: transpose via smem, coalesced store + bias ----
    float* Cs = (float*)sm;
    {
        int lr = lane >> 2;
        int lc = (lane & 3) * 2;
        #pragma unroll
        for (int mb = 0; mb < 2; mb++) {
            int row = wm + 16 * mb + lr;
            #pragma unroll
            for (int nb = 0; nb < 8; nb++) {
                int col = wn + 8 * nb + lc;
                Cs[col * CPITCH + row]           = c[mb][nb][0];
                Cs[(col + 1) * CPITCH + row]     = c[mb][nb][1];
                Cs[col * CPITCH + row + 8]       = c[mb][nb][2];
                Cs[(col + 1) * CPITCH + row + 8] = c[mb][nb][3];
            }
        }
        if (tid < 128) {
            int rg = mt * 128 + tid;
            bsm[tid] = (rg < G3) ? b_ih[rg] : 0.f;
        }
    }
    __syncthreads();
    {
        float* gxf = (float*)g_xg;
        int n  = tid >> 1;
        int rh = tid & 1;
        int tl = n >> 2, b = n & 3;
        long gbase = ((long)(t0 + tl) * NCTA + ctab) * 976 + b * 244 + mt * 128;
        int i0 = rh * 16;
        int i1 = rh ? ((mt == 0) ? 32 : 29) : 16;
        for (int i = i0; i < i1; i++) {
            float4 cv = *(float4*)(Cs + n * CPITCH + 4 * i);
            float4 bv = *(float4*)(bsm + 4 * i);
            cv.x += bv.x; cv.y += bv.y; cv.z += bv.z; cv.w += bv.w;
            *(float4*)(gxf + gbase + 4 * i) = cv;
        }
    }
}

// =====================================================================
// Kernel 2: TENSOR-CORE recurrence w/ distance-2 prefetch (R12 winner).
// =====================================================================
#define KP 208

__global__ void __launch_bounds__(512, 1) gru_tc(
    const float* __restrict__ W_hh,
    const float* __restrict__ b_hh,
    const float* __restrict__ fc_w,
    const float* __restrict__ fc_b)
{
    __shared__ __align__(16) float hgS[256 * 8];
    __shared__ __align__(16) float hsS[Hn * 8];
    __shared__ __align__(16) float4 xgs[2 * RPAD];
    __shared__ __align__(16) float bsm[256];
    __shared__ __align__(16) char hbhi[8 * KP];
    __shared__ __align__(16) char hblo[8 * KP];

    const int tid  = threadIdx.x;
    const int lane = tid & 31;
    const int w    = tid >> 5;
    const int ctab = blockIdx.x;

    for (int i = tid; i < 8 * KP / 4; i += 512) {
        ((uint32_t*)hbhi)[i] = 0u;
        ((uint32_t*)hblo)[i] = 0u;
    }
    for (int i = tid; i < Hn * 8; i += 512) hsS[i] = 0.f;
    if (tid < 256) bsm[tid] = (tid < G3) ? b_hh[tid] : 0.f;
    if (tid < RPAD) xgs[tid] = g_xg[(long)ctab * RPAD + tid];

    uint32_t ahi[6][4], alo[6][4];
    {
        char* scrh = (char*)hgS;
        char* scrl = scrh + 16 * KP;
        const int srow = tid >> 5;
        const int kbase3 = (tid & 31) * 3;
        const int aoff = (lane & 15) * KP + ((lane >> 4) * 8) * 2;
        const uint32_t scrh_u = smem_u32(scrh), scrl_u = smem_u32(scrl);

        for (int tw = 0; tw < 16; tw++) {
            __syncthreads();
            int rg = tw * 16 + srow;
            #pragma unroll
            for (int j = 0; j < 3; j++) {
                int k = kbase3 + j;
                if (k < 96) {
                    float v = (rg < G3 && k < Hn) ? W_hh[rg * Hn + k] : 0.f;
                    __nv_bfloat16 hb = __float2bfloat16(v);
                    *(__nv_bfloat16*)(scrh + srow * KP + k * 2) = hb;
                    *(__nv_bfloat16*)(scrl + srow * KP + k * 2) =
                        __float2bfloat16(v - __bfloat162float(hb));
                }
            }
            __syncthreads();
            if (w == tw) {
                #pragma unroll
                for (int kt = 0; kt < 6; kt++) {
                    ldx4(ahi[kt], scrh_u + aoff + kt * 32);
                    ldx4(alo[kt], scrl_u + aoff + kt * 32);
                }
            }
        }
    }

    float4 q1 = make_float4(0.f, 0.f, 0.f, 0.f);
    if (tid < RPAD) q1 = g_xg[((long)1 * NCTA + ctab) * RPAD + tid];
    __syncthreads();

    const uint32_t hbhi_u = smem_u32(hbhi);
    const uint32_t hblo_u = smem_u32(hblo);
    const int bofs = (lane & 7) * KP + (((lane >> 3) & 1) * 8) * 2;

    const int crow0 = w * 16 + (lane >> 2);
    const int ccol  = (lane & 3) * 2;
    const float cb0 = bsm[crow0];
    const float cb8 = bsm[crow0 + 8];

    for (int t = 0; t < Tn; t++) {
        const int cur = t & 1, nxt = cur ^ 1;

        float4 q2 = make_float4(0.f, 0.f, 0.f, 0.f);
        if (t + 2 < Tn && tid < RPAD)
            q2 = g_xg[((long)(t + 2) * NCTA + ctab) * RPAD + tid];

        float cA[4] = {0.f, 0.f, 0.f, 0.f};
        float cB[4] = {0.f, 0.f, 0.f, 0.f};
        float cC[4] = {0.f, 0.f, 0.f, 0.f};
        #pragma unroll
        for (int kt = 0; kt < 6; kt++) {
            uint32_t bh[2], bl[2];
            ldx2(bh, hbhi_u + bofs + kt * 32);
            ldx2(bl, hblo_u + bofs + kt * 32);
            mma16816(cA, ahi[kt], bh);
            mma16816(cB, alo[kt], bh);
            mma16816(cC, ahi[kt], bl);
        }
        {
            float2 s0 = make_float2(cA[0] + cB[0] + cC[0] + cb0,
                                    cA[1] + cB[1] + cC[1] + cb0);
            float2 s8 = make_float2(cA[2] + cB[2] + cC[2] + cb8,
                                    cA[3] + cB[3] + cC[3] + cb8);
            *(float2*)(hgS + crow0 * 8 + ccol)       = s0;
            *(float2*)(hgS + (crow0 + 8) * 8 + ccol) = s8;
        }
        if (t + 1 < Tn && tid < RPAD) xgs[nxt * RPAD + tid] = q1;
        __syncthreads();

        if (tid < Hn * 4) {
            int r = tid >> 2, b = tid & 3;
            const float* xgc = (const float*)(xgs + cur * RPAD) + b * 244;
            float hr = hgS[r * 8 + b];
            float hz = hgS[(Hn + r) * 8 + b];
            float hn = hgS[(2 * Hn + r) * 8 + b];
            float xr = xgc[r];
            float xz = xgc[Hn + r];
            float xn = xgc[2 * Hn + r];
            float rr = sigm(xr + hr);
            float z  = sigm(xz + hz);
            float n  = tanh_f(xn + rr * hn);
            float hnew = (1.f - z) * n + z * hsS[r * 8 + b];
            hsS[r * 8 + b] = hnew;
            __nv_bfloat16 hb = __float2bfloat16(hnew);
            *(__nv_bfloat16*)(hbhi + b * KP + r * 2) = hb;
            *(__nv_bfloat16*)(hblo + b * KP + r * 2) =
                __float2bfloat16(hnew - __bfloat162float(hb));
        }
        q1 = q2;
        __syncthreads();
    }

    if (tid < 32) {
        int b = tid >> 3, f = tid & 7;
        float a = fc_b[f];
        #pragma unroll 27
        for (int j = 0; j < Hn; j++) a += hsS[j * 8 + b] * fc_w[f * Hn + j];
        a = a * sigm(a);
        g_h8[(ctab * BPC + b) * 8 + f] = a;
    }
}

// =====================================================================
// Kernel 3: BN(8) -> fc1 -> silu -> BN(4) -> fc2. One CTA, 512 threads.
// =====================================================================
__global__ void __launch_bounds__(Bn) head_kernel(
    const float* __restrict__ g1, const float* __restrict__ beta1,
    const float* __restrict__ fc1_w, const float* __restrict__ fc1_b,
    const float* __restrict__ g2, const float* __restrict__ beta2,
    const float* __restrict__ fc2_w, const float* __restrict__ fc2_b,
    float* __restrict__ out)
{
    __shared__ float s8[Bn * 8];
    __shared__ float s4[Bn * 4];
    __shared__ float mu1[8], iv1[8], mu2[4], iv2[4];
    const int tid = threadIdx.x;

    for (int i = tid; i < Bn * 8; i += Bn) s8[i] = g_h8[i];
    __syncthreads();

    if (tid < 8) {
        float s = 0.f, ss = 0.f;
        for (int b = 0; b < Bn; b++) { float v = s8[b * 8 + tid]; s += v; ss += v * v; }
        float m = s * (1.f / Bn);
        float var = ss * (1.f / Bn) - m * m;
        mu1[tid] = m;
        iv1[tid] = rsqrtf(var + 1e-5f);
    }
    __syncthreads();

    {
        int b = tid;
        float y[8];
        #pragma unroll
        for (int f = 0; f < 8; f++)
            y[f] = (s8[b * 8 + f] - mu1[f]) * iv1[f] * g1[f] + beta1[f];
        #pragma unroll
        for (int o = 0; o < 4; o++) {
            float a = fc1_b[o];
            #pragma unroll
            for (int f = 0; f < 8; f++) a += y[f] * fc1_w[o * 8 + f];
            a = a * sigm(a);
            s4[b * 4 + o] = a;
        }
    }
    __syncthreads();

    if (tid < 4) {
        float s = 0.f, ss = 0.f;
        for (int b = 0; b < Bn; b++) { float v = s4[b * 4 + tid]; s += v; ss += v * v; }
        float m = s * (1.f / Bn);
        float var = ss * (1.f / Bn) - m * m;
        mu2[tid] = m;
        iv2[tid] = rsqrtf(var + 1e-5f);
    }
    __syncthreads();

    {
        int b = tid;
        float a = fc2_b[0];
        #pragma unroll
        for (int o = 0; o < 4; o++)
            a += ((s4[b * 4 + o] - mu2[o]) * iv2[o] * g2[o] + beta2[o]) * fc2_w[o];
        out[b] = a;
    }
}

// =====================================================================
extern "C" void kernel_launch(void* const* d_in, const int* in_sizes, int n_in,
                              void* d_out, int out_size) {
    const float* x     = (const float*)d_in[0];
    const float* W_ih  = (const float*)d_in[1];
    const float* W_hh  = (const float*)d_in[2];
    const float* b_ih  = (const float*)d_in[3];
    const float* b_hh  = (const float*)d_in[4];
    const float* fc_w  = (const float*)d_in[5];
    const float* fc_b  = (const float*)d_in[6];
    const float* g1    = (const float*)d_in[7];
    const float* beta1 = (const float*)d_in[8];
    const float* fc1_w = (const float*)d_in[9];
    const float* fc1_b = (const float*)d_in[10];
    const float* g2    = (const float*)d_in[11];
    const float* beta2 = (const float*)d_in[12];
    const float* fc2_w = (const float*)d_in[13];
    const float* fc2_b = (const float*)d_in[14];
    float* out = (float*)d_out;

    cudaFuncSetAttribute(xg_mma, cudaFuncAttributeMaxDynamicSharedMemorySize, SM_MMA_BYTES);

    xg_mma<<<dim3(NCTA, 32, 2), 256, SM_MMA_BYTES>>>(x, W_ih, b_ih);
    gru_tc<<<NCTA, 512>>>(W_hh, b_hh, fc_w, fc_b);
    head_kernel<<<1, Bn>>>(g1, beta1, fc1_w, fc1_b, g2, beta2, fc2_w, fc2_b, out);
}